// round 16
// baseline (speedup 1.0000x reference)
#include <cuda_runtime.h>
#include <cuda_fp16.h>
#include <cstdint>
#include <math.h>

#define DINLINE __device__ __forceinline__

constexpr int BATCH = 2, SEQ = 2048, H = 4096, I = 16384;
constexpr int M = BATCH * SEQ;
constexpr float EPS = 1e-5f;

// ---------------- GEMM tiling: 128x128 CTA tile, 64x64 warp tile, 128 threads ----
constexpr int BM = 128, BN = 128, BK = 64, PSTAGES = 3;
constexpr int LDA_H = BK + 8;                 // 72 halfs (144 B row)
constexpr int LDB_H = BN + 8;                 // 136 halfs (272 B row)
constexpr int A_ST = BM * LDA_H * 2;          // 18432 B / stage
constexpr int B_ST = BK * LDB_H * 2;          // 17408 B / stage
constexpr int SM_A = 0;
constexpr int SM_B = PSTAGES * A_ST;          // 55296
constexpr int SMEM_SZ = SM_B + PSTAGES * B_ST;// 107520 B (2 CTAs/SM)

// ---------------- scratch (no allocation) ----------------
__device__ float  g_pre[(size_t)M * H];          // fp32 residual stream
__device__ __half g_ln [(size_t)M * H];          // fp16 LN output (GEMM1 A)
__device__ __half g_h  [(size_t)M * I];          // fp16 gelu(fc1)  (GEMM2 A)
__device__ __half g_w1 [(size_t)H * I];          // fp16 inter_w  [K=H][N=I]
__device__ __half g_w2 [(size_t)H * I];          // fp16 output_w [K=I][N=H]

// ---------------- PTX helpers (baseline sm_80 features only) ----------------
DINLINE uint32_t smem_u32(const void* p) {
    uint32_t a;
    asm("{ .reg .u64 t; cvta.to.shared.u64 t, %1; cvt.u32.u64 %0, t; }" : "=r"(a) : "l"(p));
    return a;
}
DINLINE void cp16(uint32_t dst, const void* src) {
    asm volatile("cp.async.cg.shared.global [%0], [%1], 16;" :: "r"(dst), "l"(src));
}
DINLINE void cp_commit() { asm volatile("cp.async.commit_group;" ::: "memory"); }
DINLINE void cp_wait1()  { asm volatile("cp.async.wait_group 1;" ::: "memory"); }

DINLINE void ldsm4(uint32_t* r, uint32_t addr) {
    asm volatile("ldmatrix.sync.aligned.m8n8.x4.shared.b16 {%0,%1,%2,%3}, [%4];"
                 : "=r"(r[0]), "=r"(r[1]), "=r"(r[2]), "=r"(r[3]) : "r"(addr));
}
DINLINE void ldsm4t(uint32_t* r, uint32_t addr) {
    asm volatile("ldmatrix.sync.aligned.m8n8.x4.trans.shared.b16 {%0,%1,%2,%3}, [%4];"
                 : "=r"(r[0]), "=r"(r[1]), "=r"(r[2]), "=r"(r[3]) : "r"(addr));
}
DINLINE void mma16816(float* d, const uint32_t* a, uint32_t b0, uint32_t b1) {
    asm volatile("mma.sync.aligned.m16n8k16.row.col.f32.f16.f16.f32 "
                 "{%0,%1,%2,%3}, {%4,%5,%6,%7}, {%8,%9}, {%0,%1,%2,%3};"
                 : "+f"(d[0]), "+f"(d[1]), "+f"(d[2]), "+f"(d[3])
                 : "r"(a[0]), "r"(a[1]), "r"(a[2]), "r"(a[3]), "r"(b0), "r"(b1));
}
DINLINE float gelu_exact(float x) {
    return 0.5f * x * (1.0f + erff(x * 0.7071067811865475f));
}

// ---------------- fused add + LayerNorm (+ w1 fp32->fp16 side job) ----------------
__global__ void __launch_bounds__(256) ln_fused(
    const float* __restrict__ inp, const float* __restrict__ res,
    const float* __restrict__ bias, const float* __restrict__ gw,
    const float* __restrict__ gb,
    const float4* __restrict__ wsrc, __half2* __restrict__ wdst)
{
    int row = blockIdx.x, t = threadIdx.x;
    const float4* pi = (const float4*)(inp + (size_t)row * H);
    const float4* pr = (const float4*)(res + (size_t)row * H);
    const float4* pb = (const float4*)bias;
    float4 v[4];
    float s = 0.f, q = 0.f;
#pragma unroll
    for (int k = 0; k < 4; k++) {
        int u = t + k * 256;
        float4 a = pi[u], b = pr[u], c = pb[u];
        float4 p;
        p.x = a.x + b.x + c.x; p.y = a.y + b.y + c.y;
        p.z = a.z + b.z + c.z; p.w = a.w + b.w + c.w;
        v[k] = p;
        s += p.x + p.y + p.z + p.w;
        q += p.x * p.x + p.y * p.y + p.z * p.z + p.w * p.w;
    }
#pragma unroll
    for (int o = 16; o; o >>= 1) {
        s += __shfl_xor_sync(0xFFFFFFFFu, s, o);
        q += __shfl_xor_sync(0xFFFFFFFFu, q, o);
    }
    __shared__ float2 red[8];
    __shared__ float2 mv;
    int wid = t >> 5, lid = t & 31;
    if (lid == 0) red[wid] = make_float2(s, q);
    __syncthreads();
    if (t == 0) {
        float S = 0.f, Q = 0.f;
#pragma unroll
        for (int w = 0; w < 8; w++) { S += red[w].x; Q += red[w].y; }
        float mu = S / (float)H;
        float var = Q / (float)H - mu * mu;
        mv = make_float2(mu, rsqrtf(var + EPS));
    }
    __syncthreads();
    float mu = mv.x, rs = mv.y;
    float4*   ppre = (float4*)(g_pre + (size_t)row * H);
    __half2*  pln  = (__half2*)(g_ln + (size_t)row * H);
    const float4* pgw = (const float4*)gw;
    const float4* pgb = (const float4*)gb;
#pragma unroll
    for (int k = 0; k < 4; k++) {
        int u = t + k * 256;
        ppre[u] = v[k];
        float4 w = pgw[u], b = pgb[u];
        float o0 = (v[k].x - mu) * rs * w.x + b.x;
        float o1 = (v[k].y - mu) * rs * w.y + b.y;
        float o2 = (v[k].z - mu) * rs * w.z + b.z;
        float o3 = (v[k].w - mu) * rs * w.w + b.w;
        pln[2 * u]     = __floats2half2_rn(o0, o1);
        pln[2 * u + 1] = __floats2half2_rn(o2, o3);
    }

    // side job: convert this block's slice of inter_w (fp32 -> fp16).
    // 4096 blocks x 4096 float4 = all of H*I.
    {
        size_t base = (size_t)row * 4096 + t;
#pragma unroll 4
        for (int i = 0; i < 16; i++) {
            size_t idx = base + (size_t)i * 256;
            float4 w = __ldg(&wsrc[idx]);
            wdst[2 * idx]     = __floats2half2_rn(w.x, w.y);
            wdst[2 * idx + 1] = __floats2half2_rn(w.z, w.w);
        }
    }
}

// ---------------- GEMM stage load (128 threads, BK=64, compile-time K/N) ----------
template <int K, int N>
DINLINE void load_stage(uint32_t sb, int stage, int chunk,
                        const __half* __restrict__ A, const __half* __restrict__ B,
                        int m0, int n0, int tid)
{
    int k0 = chunk * BK;
    // A tile: 128 rows x 8 x 16B = 1024 ops
    {
        uint32_t base = sb + SM_A + stage * A_ST;
        const __half* src = A + (size_t)m0 * K + k0;
#pragma unroll
        for (int i = 0; i < 8; i++) {
            int idx = tid + i * 128;          // 0..1023
            int row = idx >> 3, c = idx & 7;
            cp16(base + (uint32_t)(row * (LDA_H * 2) + c * 16),
                 src + (size_t)row * K + c * 8);
        }
    }
    // B tile: 64 rows x 16 x 16B = 1024 ops
    {
        uint32_t base = sb + SM_B + stage * B_ST;
        const __half* src = B + (size_t)k0 * N + n0;
#pragma unroll
        for (int i = 0; i < 8; i++) {
            int idx = tid + i * 128;          // 0..1023
            int row = idx >> 4, c = idx & 15;
            cp16(base + (uint32_t)(row * (LDB_H * 2) + c * 16),
                 src + (size_t)row * N + c * 8);
        }
    }
}

template <int GRIDN>
DINLINE void tile_coords(int tile, int& m0, int& n0) {
    int group = tile / (8 * GRIDN);
    int rem = tile - group * 8 * GRIDN;
    m0 = (group * 8 + (rem & 7)) * BM;
    n0 = (rem >> 3) * BN;
}

struct Frag {
    uint32_t a[4][4];
    uint32_t b[4][4];
};

DINLINE void load_frags(Frag& f, uint32_t sb, int stage, int ks,
                        uint32_t a_off, uint32_t b_off)
{
    uint32_t abase = sb + SM_A + stage * A_ST + a_off + ks * 32;
#pragma unroll
    for (int mi = 0; mi < 4; mi++)
        ldsm4(f.a[mi], abase + mi * 16 * LDA_H * 2);
    uint32_t bbase = sb + SM_B + stage * B_ST + b_off + ks * 16 * LDB_H * 2;
#pragma unroll
    for (int nq = 0; nq < 4; nq++)
        ldsm4t(f.b[nq], bbase + nq * 32);
}

DINLINE void mma_frags(float acc[4][8][4], const Frag& f) {
#pragma unroll
    for (int mi = 0; mi < 4; mi++)
#pragma unroll
        for (int nq = 0; nq < 4; nq++) {
            mma16816(acc[mi][2 * nq],     f.a[mi], f.b[nq][0], f.b[nq][1]);
            mma16816(acc[mi][2 * nq + 1], f.a[mi], f.b[nq][2], f.b[nq][3]);
        }
}

// ---------------- GEMM: C[M,N] = A[M,K] * B[K,N] (+epilogue) ----------------
// EPI 0: C = fp16( gelu(acc + bias[n]) )  (GEMM1 -> g_h) ; also converts a slice
//        of output_w fp32->fp16 (hidden under the pipeline; consumed by GEMM2)
// EPI 1: C = fp32( acc + bias[n] + pre[m,n] )   (GEMM2 -> out)
template <int EPI, int K, int N, int GRIDN>
__global__ void __launch_bounds__(128, 2) gemm_f16(
    const __half* __restrict__ A, const __half* __restrict__ B,
    const float* __restrict__ bias, const float* __restrict__ pre,
    void* __restrict__ Cout,
    const float4* __restrict__ wsrc, __half2* __restrict__ wdst)
{
    extern __shared__ char smem[];
    uint32_t sb = smem_u32(smem);
    int tid = threadIdx.x, lane = tid & 31, wid = tid >> 5;
    int wm = wid & 1, wn = wid >> 1;          // 2x2 warp grid, warp tile 64x64

    int g = lane >> 3, r = lane & 7;
    uint32_t a_off = (uint32_t)(((wm * 64 + (g & 1) * 8 + r) * LDA_H + (g >> 1) * 8) * 2);
    uint32_t b_off = (uint32_t)((((g & 1) * 8 + r) * LDB_H + wn * 64 + (g >> 1) * 8) * 2);

    int m0, n0;
    tile_coords<GRIDN>(blockIdx.x, m0, n0);

    constexpr int NC = K / BK;

    // prologue: 2 stages in flight (issued first so the convert below overlaps them)
    load_stage<K, N>(sb, 0, 0, A, B, m0, n0, tid);
    cp_commit();
    load_stage<K, N>(sb, 1, 1, A, B, m0, n0, tid);
    cp_commit();

    // GEMM1 side-job: convert this block's slice of output_w (fp32 -> fp16).
    if (EPI == 0) {
        size_t base = (size_t)blockIdx.x * 4096 + tid;
#pragma unroll 8
        for (int i = 0; i < 32; i++) {
            size_t idx = base + (size_t)i * 128;
            float4 v = __ldg(&wsrc[idx]);
            wdst[2 * idx]     = __floats2half2_rn(v.x, v.y);
            wdst[2 * idx + 1] = __floats2half2_rn(v.z, v.w);
        }
    }

    float acc[4][8][4];
#pragma unroll
    for (int a = 0; a < 4; a++)
#pragma unroll
        for (int b = 0; b < 8; b++)
#pragma unroll
            for (int c = 0; c < 4; c++) acc[a][b][c] = 0.f;

    cp_wait1();
    __syncthreads();

    Frag f0, f1;
    load_frags(f0, sb, 0, 0, a_off, b_off);

#pragma unroll 1
    for (int c = 0; c < NC; c++) {
        int stage = c % PSTAGES;

        // ks0: prefetch ks1 frags, issue next gmem stage, compute ks0
        load_frags(f1, sb, stage, 1, a_off, b_off);
        int nxt = c + PSTAGES - 1;
        if (nxt < NC) load_stage<K, N>(sb, nxt % PSTAGES, nxt, A, B, m0, n0, tid);
        cp_commit();
        mma_frags(acc, f0);

        // ks1
        load_frags(f0, sb, stage, 2, a_off, b_off);
        mma_frags(acc, f1);

        // ks2
        load_frags(f1, sb, stage, 3, a_off, b_off);
        mma_frags(acc, f0);

        // ks3: compute BEFORE the wait/bar (no smem dependence -> tensor pipe
        // stays busy during barrier); then wait, sync, prefetch next chunk ks0
        mma_frags(acc, f1);
        cp_wait1();
        __syncthreads();
        int nstage = (c + 1 < NC) ? ((c + 1) % PSTAGES) : stage;
        load_frags(f0, sb, nstage, 0, a_off, b_off);
    }

    // epilogue (registers only; bias hoisted)
    int gi = lane >> 2, t4 = lane & 3;
    float bv[8][2];
#pragma unroll
    for (int ni = 0; ni < 8; ni++) {
        int col = n0 + wn * 64 + ni * 8 + t4 * 2;
        bv[ni][0] = __ldg(bias + col);
        bv[ni][1] = __ldg(bias + col + 1);
    }
#pragma unroll
    for (int mi = 0; mi < 4; mi++) {
#pragma unroll
        for (int ni = 0; ni < 8; ni++) {
            int row = m0 + wm * 64 + mi * 16 + gi;
            int col = n0 + wn * 64 + ni * 8 + t4 * 2;
            float b0 = bv[ni][0], b1 = bv[ni][1];
            float* ac = acc[mi][ni];
            if (EPI == 0) {
                __half2* hp = (__half2*)Cout;
                float v0 = gelu_exact(ac[0] + b0);
                float v1 = gelu_exact(ac[1] + b1);
                hp[((size_t)row * N + col) >> 1] = __floats2half2_rn(v0, v1);
                float v2 = gelu_exact(ac[2] + b0);
                float v3 = gelu_exact(ac[3] + b1);
                hp[((size_t)(row + 8) * N + col) >> 1] = __floats2half2_rn(v2, v3);
            } else {
                float* fp = (float*)Cout;
                float2 p0 = *(const float2*)(pre + (size_t)row * N + col);
                float2 p1 = *(const float2*)(pre + (size_t)(row + 8) * N + col);
                float2 o0 = make_float2(ac[0] + b0 + p0.x, ac[1] + b1 + p0.y);
                float2 o1 = make_float2(ac[2] + b0 + p1.x, ac[3] + b1 + p1.y);
                *(float2*)(fp + (size_t)row * N + col) = o0;
                *(float2*)(fp + (size_t)(row + 8) * N + col) = o1;
            }
        }
    }
}

// ---------------- launch ----------------
extern "C" void kernel_launch(void* const* d_in, const int* in_sizes, int n_in,
                              void* d_out, int out_size)
{
    const float* input     = (const float*)d_in[0];
    const float* residual  = (const float*)d_in[1];
    const float* attn_bias = (const float*)d_in[3];
    const float* attn_nw   = (const float*)d_in[5];
    const float* attn_nb   = (const float*)d_in[6];
    const float* inter_w   = (const float*)d_in[7];
    const float* inter_b   = (const float*)d_in[8];
    const float* output_w  = (const float*)d_in[9];
    const float* output_b  = (const float*)d_in[10];
    float* out = (float*)d_out;

    float *pre; __half *ln, *h, *w1, *w2;
    cudaGetSymbolAddress((void**)&pre, g_pre);
    cudaGetSymbolAddress((void**)&ln,  g_ln);
    cudaGetSymbolAddress((void**)&h,   g_h);
    cudaGetSymbolAddress((void**)&w1,  g_w1);
    cudaGetSymbolAddress((void**)&w2,  g_w2);

    // LN + w1 convert fused
    ln_fused<<<M, 256>>>(input, residual, attn_bias, attn_nw, attn_nb,
                         (const float4*)inter_w, (__half2*)w1);

    cudaFuncSetAttribute((const void*)gemm_f16<0, H, I, 128>,
                         cudaFuncAttributeMaxDynamicSharedMemorySize, SMEM_SZ);
    cudaFuncSetAttribute((const void*)gemm_f16<1, I, H, 32>,
                         cudaFuncAttributeMaxDynamicSharedMemorySize, SMEM_SZ);

    // GEMM1: [M,H] x [H,I] -> g_h (fp16, gelu); also converts output_w -> g_w2
    gemm_f16<0, H, I, 128><<<4096, 128, SMEM_SZ>>>(
        ln, w1, inter_b, nullptr, h, (const float4*)output_w, (__half2*)w2);
    // GEMM2: [M,I] x [I,H] -> out (fp32, +bias+pre)
    gemm_f16<1, I, H, 32><<<1024, 128, SMEM_SZ>>>(
        h, w2, output_b, pre, out, nullptr, nullptr);
}

// round 17
// speedup vs baseline: 1.0153x; 1.0153x over previous
#include <cuda_runtime.h>
#include <cuda_fp16.h>
#include <cstdint>
#include <math.h>

#define DINLINE __device__ __forceinline__

constexpr int BATCH = 2, SEQ = 2048, H = 4096, I = 16384;
constexpr int M = BATCH * SEQ;
constexpr float EPS = 1e-5f;

// ---------------- GEMM tiling: 128x128 CTA tile, 64x64 warp tile, 128 threads ----
constexpr int BM = 128, BN = 128, BK = 64, PSTAGES = 3;
constexpr int LDA_H = BK + 8;                 // 72 halfs (144 B row)
constexpr int LDB_H = BN + 8;                 // 136 halfs (272 B row)
constexpr int A_ST = BM * LDA_H * 2;          // 18432 B / stage
constexpr int B_ST = BK * LDB_H * 2;          // 17408 B / stage
constexpr int SM_A = 0;
constexpr int SM_B = PSTAGES * A_ST;          // 55296
constexpr int SMEM_SZ = SM_B + PSTAGES * B_ST;// 107520 B (2 CTAs/SM)

// ---------------- scratch (no allocation) ----------------
__device__ __half g_ln [(size_t)M * H];          // fp16 LN output (GEMM1 A)
__device__ __half g_h  [(size_t)M * I];          // fp16 gelu(fc1)  (GEMM2 A)
__device__ __half g_w1 [(size_t)H * I];          // fp16 inter_w  [K=H][N=I]
__device__ __half g_w2 [(size_t)H * I];          // fp16 output_w [K=I][N=H]

// ---------------- PTX helpers (baseline sm_80 features only) ----------------
DINLINE uint32_t smem_u32(const void* p) {
    uint32_t a;
    asm("{ .reg .u64 t; cvta.to.shared.u64 t, %1; cvt.u32.u64 %0, t; }" : "=r"(a) : "l"(p));
    return a;
}
DINLINE void cp16(uint32_t dst, const void* src) {
    asm volatile("cp.async.cg.shared.global [%0], [%1], 16;" :: "r"(dst), "l"(src));
}
DINLINE void cp_commit() { asm volatile("cp.async.commit_group;" ::: "memory"); }
DINLINE void cp_wait1()  { asm volatile("cp.async.wait_group 1;" ::: "memory"); }

DINLINE void ldsm4(uint32_t* r, uint32_t addr) {
    asm volatile("ldmatrix.sync.aligned.m8n8.x4.shared.b16 {%0,%1,%2,%3}, [%4];"
                 : "=r"(r[0]), "=r"(r[1]), "=r"(r[2]), "=r"(r[3]) : "r"(addr));
}
DINLINE void ldsm4t(uint32_t* r, uint32_t addr) {
    asm volatile("ldmatrix.sync.aligned.m8n8.x4.trans.shared.b16 {%0,%1,%2,%3}, [%4];"
                 : "=r"(r[0]), "=r"(r[1]), "=r"(r[2]), "=r"(r[3]) : "r"(addr));
}
DINLINE void mma16816(float* d, const uint32_t* a, uint32_t b0, uint32_t b1) {
    asm volatile("mma.sync.aligned.m16n8k16.row.col.f32.f16.f16.f32 "
                 "{%0,%1,%2,%3}, {%4,%5,%6,%7}, {%8,%9}, {%0,%1,%2,%3};"
                 : "+f"(d[0]), "+f"(d[1]), "+f"(d[2]), "+f"(d[3])
                 : "r"(a[0]), "r"(a[1]), "r"(a[2]), "r"(a[3]), "r"(b0), "r"(b1));
}
DINLINE float gelu_exact(float x) {
    return 0.5f * x * (1.0f + erff(x * 0.7071067811865475f));
}

// ---------------- fused add + LayerNorm (no residual-stream store) ----------------
__global__ void __launch_bounds__(256) ln_fused(
    const float* __restrict__ inp, const float* __restrict__ res,
    const float* __restrict__ bias, const float* __restrict__ gw,
    const float* __restrict__ gb)
{
    int row = blockIdx.x, t = threadIdx.x;
    const float4* pi = (const float4*)(inp + (size_t)row * H);
    const float4* pr = (const float4*)(res + (size_t)row * H);
    const float4* pb = (const float4*)bias;
    float4 v[4];
    float s = 0.f, q = 0.f;
#pragma unroll
    for (int k = 0; k < 4; k++) {
        int u = t + k * 256;
        float4 a = pi[u], b = pr[u], c = pb[u];
        float4 p;
        p.x = a.x + b.x + c.x; p.y = a.y + b.y + c.y;
        p.z = a.z + b.z + c.z; p.w = a.w + b.w + c.w;
        v[k] = p;
        s += p.x + p.y + p.z + p.w;
        q += p.x * p.x + p.y * p.y + p.z * p.z + p.w * p.w;
    }
#pragma unroll
    for (int o = 16; o; o >>= 1) {
        s += __shfl_xor_sync(0xFFFFFFFFu, s, o);
        q += __shfl_xor_sync(0xFFFFFFFFu, q, o);
    }
    __shared__ float2 red[8];
    __shared__ float2 mv;
    int wid = t >> 5, lid = t & 31;
    if (lid == 0) red[wid] = make_float2(s, q);
    __syncthreads();
    if (t == 0) {
        float S = 0.f, Q = 0.f;
#pragma unroll
        for (int w = 0; w < 8; w++) { S += red[w].x; Q += red[w].y; }
        float mu = S / (float)H;
        float var = Q / (float)H - mu * mu;
        mv = make_float2(mu, rsqrtf(var + EPS));
    }
    __syncthreads();
    float mu = mv.x, rs = mv.y;
    __half2* pln = (__half2*)(g_ln + (size_t)row * H);
    const float4* pgw = (const float4*)gw;
    const float4* pgb = (const float4*)gb;
#pragma unroll
    for (int k = 0; k < 4; k++) {
        int u = t + k * 256;
        float4 w = pgw[u], b = pgb[u];
        float o0 = (v[k].x - mu) * rs * w.x + b.x;
        float o1 = (v[k].y - mu) * rs * w.y + b.y;
        float o2 = (v[k].z - mu) * rs * w.z + b.z;
        float o3 = (v[k].w - mu) * rs * w.w + b.w;
        pln[2 * u]     = __floats2half2_rn(o0, o1);
        pln[2 * u + 1] = __floats2half2_rn(o2, o3);
    }
}

// ---------------- fp32 -> fp16 weight convert (for inter_w) ----------------
__global__ void __launch_bounds__(256) f2h(
    const float4* __restrict__ src, __half2* __restrict__ dst, int n4)
{
    int i = blockIdx.x * 256 + threadIdx.x;
    if (i < n4) {
        float4 v = src[i];
        dst[2 * i]     = __floats2half2_rn(v.x, v.y);
        dst[2 * i + 1] = __floats2half2_rn(v.z, v.w);
    }
}

// ---------------- GEMM stage load (128 threads, BK=64, compile-time K/N) ----------
template <int K, int N>
DINLINE void load_stage(uint32_t sb, int stage, int chunk,
                        const __half* __restrict__ A, const __half* __restrict__ B,
                        int m0, int n0, int tid)
{
    int k0 = chunk * BK;
    // A tile: 128 rows x 8 x 16B = 1024 ops
    {
        uint32_t base = sb + SM_A + stage * A_ST;
        const __half* src = A + (size_t)m0 * K + k0;
#pragma unroll
        for (int i = 0; i < 8; i++) {
            int idx = tid + i * 128;          // 0..1023
            int row = idx >> 3, c = idx & 7;
            cp16(base + (uint32_t)(row * (LDA_H * 2) + c * 16),
                 src + (size_t)row * K + c * 8);
        }
    }
    // B tile: 64 rows x 16 x 16B = 1024 ops
    {
        uint32_t base = sb + SM_B + stage * B_ST;
        const __half* src = B + (size_t)k0 * N + n0;
#pragma unroll
        for (int i = 0; i < 8; i++) {
            int idx = tid + i * 128;          // 0..1023
            int row = idx >> 4, c = idx & 15;
            cp16(base + (uint32_t)(row * (LDB_H * 2) + c * 16),
                 src + (size_t)row * N + c * 8);
        }
    }
}

template <int GRIDN>
DINLINE void tile_coords(int tile, int& m0, int& n0) {
    int group = tile / (8 * GRIDN);
    int rem = tile - group * 8 * GRIDN;
    m0 = (group * 8 + (rem & 7)) * BM;
    n0 = (rem >> 3) * BN;
}

struct Frag {
    uint32_t a[4][4];
    uint32_t b[4][4];
};

DINLINE void load_frags(Frag& f, uint32_t sb, int stage, int ks,
                        uint32_t a_off, uint32_t b_off)
{
    uint32_t abase = sb + SM_A + stage * A_ST + a_off + ks * 32;
#pragma unroll
    for (int mi = 0; mi < 4; mi++)
        ldsm4(f.a[mi], abase + mi * 16 * LDA_H * 2);
    uint32_t bbase = sb + SM_B + stage * B_ST + b_off + ks * 16 * LDB_H * 2;
#pragma unroll
    for (int nq = 0; nq < 4; nq++)
        ldsm4t(f.b[nq], bbase + nq * 32);
}

DINLINE void mma_frags(float acc[4][8][4], const Frag& f) {
#pragma unroll
    for (int mi = 0; mi < 4; mi++)
#pragma unroll
        for (int nq = 0; nq < 4; nq++) {
            mma16816(acc[mi][2 * nq],     f.a[mi], f.b[nq][0], f.b[nq][1]);
            mma16816(acc[mi][2 * nq + 1], f.a[mi], f.b[nq][2], f.b[nq][3]);
        }
}

// ---------------- GEMM: C[M,N] = A[M,K] * B[K,N] (+epilogue) ----------------
// EPI 0: C = fp16( gelu(acc + bias[n]) )  (GEMM1 -> g_h) ; also converts a slice
//        of output_w fp32->fp16 (hidden under the pipeline; consumed by GEMM2)
// EPI 1: C = fp32( acc + (output_b+attn_bias)[n] + input[m,n] + residual[m,n] )
template <int EPI, int K, int N, int GRIDN>
__global__ void __launch_bounds__(128, 2) gemm_f16(
    const __half* __restrict__ A, const __half* __restrict__ B,
    const float* __restrict__ bias, const float* __restrict__ abias,
    const float* __restrict__ in0, const float* __restrict__ in1,
    void* __restrict__ Cout,
    const float4* __restrict__ wsrc, __half2* __restrict__ wdst)
{
    extern __shared__ char smem[];
    uint32_t sb = smem_u32(smem);
    int tid = threadIdx.x, lane = tid & 31, wid = tid >> 5;
    int wm = wid & 1, wn = wid >> 1;          // 2x2 warp grid, warp tile 64x64

    int g = lane >> 3, r = lane & 7;
    uint32_t a_off = (uint32_t)(((wm * 64 + (g & 1) * 8 + r) * LDA_H + (g >> 1) * 8) * 2);
    uint32_t b_off = (uint32_t)((((g & 1) * 8 + r) * LDB_H + wn * 64 + (g >> 1) * 8) * 2);

    int m0, n0;
    tile_coords<GRIDN>(blockIdx.x, m0, n0);

    constexpr int NC = K / BK;

    // prologue: 2 stages in flight (issued first so the convert below overlaps them)
    load_stage<K, N>(sb, 0, 0, A, B, m0, n0, tid);
    cp_commit();
    load_stage<K, N>(sb, 1, 1, A, B, m0, n0, tid);
    cp_commit();

    // GEMM1 side-job: convert this block's slice of output_w (fp32 -> fp16).
    if (EPI == 0) {
        size_t base = (size_t)blockIdx.x * 4096 + tid;
#pragma unroll 8
        for (int i = 0; i < 32; i++) {
            size_t idx = base + (size_t)i * 128;
            float4 v = __ldg(&wsrc[idx]);
            wdst[2 * idx]     = __floats2half2_rn(v.x, v.y);
            wdst[2 * idx + 1] = __floats2half2_rn(v.z, v.w);
        }
    }

    float acc[4][8][4];
#pragma unroll
    for (int a = 0; a < 4; a++)
#pragma unroll
        for (int b = 0; b < 8; b++)
#pragma unroll
            for (int c = 0; c < 4; c++) acc[a][b][c] = 0.f;

    cp_wait1();
    __syncthreads();

    Frag f0, f1;
    load_frags(f0, sb, 0, 0, a_off, b_off);

#pragma unroll 1
    for (int c = 0; c < NC; c++) {
        int stage = c % PSTAGES;

        // ks0: prefetch ks1 frags, issue next gmem stage, compute ks0
        load_frags(f1, sb, stage, 1, a_off, b_off);
        int nxt = c + PSTAGES - 1;
        if (nxt < NC) load_stage<K, N>(sb, nxt % PSTAGES, nxt, A, B, m0, n0, tid);
        cp_commit();
        mma_frags(acc, f0);

        // ks1
        load_frags(f0, sb, stage, 2, a_off, b_off);
        mma_frags(acc, f1);

        // ks2
        load_frags(f1, sb, stage, 3, a_off, b_off);
        mma_frags(acc, f0);

        // ks3: wait next stage ready, sync, prefetch next chunk ks0, compute ks3
        cp_wait1();
        __syncthreads();
        int nstage = (c + 1 < NC) ? ((c + 1) % PSTAGES) : stage;
        load_frags(f0, sb, nstage, 0, a_off, b_off);
        mma_frags(acc, f1);
    }

    // epilogue (registers only; bias hoisted)
    int gi = lane >> 2, t4 = lane & 3;
    float bv[8][2];
#pragma unroll
    for (int ni = 0; ni < 8; ni++) {
        int col = n0 + wn * 64 + ni * 8 + t4 * 2;
        float e0 = __ldg(bias + col), e1 = __ldg(bias + col + 1);
        if (EPI == 1) { e0 += __ldg(abias + col); e1 += __ldg(abias + col + 1); }
        bv[ni][0] = e0;
        bv[ni][1] = e1;
    }
#pragma unroll
    for (int mi = 0; mi < 4; mi++) {
#pragma unroll
        for (int ni = 0; ni < 8; ni++) {
            int row = m0 + wm * 64 + mi * 16 + gi;
            int col = n0 + wn * 64 + ni * 8 + t4 * 2;
            float b0 = bv[ni][0], b1 = bv[ni][1];
            float* ac = acc[mi][ni];
            if (EPI == 0) {
                __half2* hp = (__half2*)Cout;
                float v0 = gelu_exact(ac[0] + b0);
                float v1 = gelu_exact(ac[1] + b1);
                hp[((size_t)row * N + col) >> 1] = __floats2half2_rn(v0, v1);
                float v2 = gelu_exact(ac[2] + b0);
                float v3 = gelu_exact(ac[3] + b1);
                hp[((size_t)(row + 8) * N + col) >> 1] = __floats2half2_rn(v2, v3);
            } else {
                float* fp = (float*)Cout;
                size_t o0i = (size_t)row * N + col;
                size_t o1i = (size_t)(row + 8) * N + col;
                float2 i00 = *(const float2*)(in0 + o0i);
                float2 i01 = *(const float2*)(in1 + o0i);
                float2 i10 = *(const float2*)(in0 + o1i);
                float2 i11 = *(const float2*)(in1 + o1i);
                float2 o0 = make_float2(ac[0] + b0 + i00.x + i01.x,
                                        ac[1] + b1 + i00.y + i01.y);
                float2 o1 = make_float2(ac[2] + b0 + i10.x + i11.x,
                                        ac[3] + b1 + i10.y + i11.y);
                *(float2*)(fp + o0i) = o0;
                *(float2*)(fp + o1i) = o1;
            }
        }
    }
}

// ---------------- launch ----------------
extern "C" void kernel_launch(void* const* d_in, const int* in_sizes, int n_in,
                              void* d_out, int out_size)
{
    const float* input     = (const float*)d_in[0];
    const float* residual  = (const float*)d_in[1];
    const float* attn_bias = (const float*)d_in[3];
    const float* attn_nw   = (const float*)d_in[5];
    const float* attn_nb   = (const float*)d_in[6];
    const float* inter_w   = (const float*)d_in[7];
    const float* inter_b   = (const float*)d_in[8];
    const float* output_w  = (const float*)d_in[9];
    const float* output_b  = (const float*)d_in[10];
    float* out = (float*)d_out;

    __half *ln, *h, *w1, *w2;
    cudaGetSymbolAddress((void**)&ln,  g_ln);
    cudaGetSymbolAddress((void**)&h,   g_h);
    cudaGetSymbolAddress((void**)&w1,  g_w1);
    cudaGetSymbolAddress((void**)&w2,  g_w2);

    ln_fused<<<M, 256>>>(input, residual, attn_bias, attn_nw, attn_nb);

    int n4 = (H * I) / 4;
    f2h<<<(n4 + 255) / 256, 256>>>((const float4*)inter_w, (__half2*)w1, n4);

    cudaFuncSetAttribute((const void*)gemm_f16<0, H, I, 128>,
                         cudaFuncAttributeMaxDynamicSharedMemorySize, SMEM_SZ);
    cudaFuncSetAttribute((const void*)gemm_f16<1, I, H, 32>,
                         cudaFuncAttributeMaxDynamicSharedMemorySize, SMEM_SZ);

    // GEMM1: [M,H] x [H,I] -> g_h (fp16, gelu); also converts output_w -> g_w2
    gemm_f16<0, H, I, 128><<<4096, 128, SMEM_SZ>>>(
        ln, w1, inter_b, nullptr, nullptr, nullptr, h,
        (const float4*)output_w, (__half2*)w2);
    // GEMM2: [M,I] x [I,H] -> out (fp32, + output_b + attn_bias + input + residual)
    gemm_f16<1, I, H, 32><<<1024, 128, SMEM_SZ>>>(
        h, w2, output_b, attn_bias, input, residual, out, nullptr, nullptr);
}